// round 2
// baseline (speedup 1.0000x reference)
#include <cuda_runtime.h>

// Problem constants (fixed by the dataset)
#define NN 2048   // reservoir size
#define BB 256    // batch
#define TT 256    // timesteps
#define CC 2      // channels
#define SLOPE 8.0f

// Scratch state buffers (allocation-free rule -> __device__ globals)
__device__ float g_state[BB * NN];   // state after each step
__device__ float g_sprime[BB * NN];  // s' = state + mask * ext

// ---------------------------------------------------------------------------
__global__ void zero_kernel(float* __restrict__ out, int n) {
    int i = blockIdx.x * blockDim.x + threadIdx.x;
    if (i < n) out[i] = 0.0f;
}

// ---------------------------------------------------------------------------
// s'[b,m] = s[b,m] + mask[m] * (x0[b]*enc[0,m] + x1[b]*enc[1,m])
__global__ void prep_kernel(const float* __restrict__ state0,
                            const float* __restrict__ inputs,
                            const float* __restrict__ mask,
                            const float* __restrict__ enc,
                            int t) {
    int i = blockIdx.x * blockDim.x + threadIdx.x;  // over B*N
    int b = i >> 11;        // / NN
    int m = i & (NN - 1);   // % NN
    const float* s = (t == 0) ? state0 : g_state;
    float x0 = inputs[b * TT + t];            // c=0 : (0*BB+b)*TT + t
    float x1 = inputs[(BB + b) * TT + t];     // c=1
    g_sprime[i] = s[i] + mask[m] * (x0 * enc[m] + x1 * enc[NN + m]);
}

// ---------------------------------------------------------------------------
// Fused step: pre = s' @ W^T ; ns = mask*(bias + sigmoid(SLOPE*(pre-thr)))
//             g_state = ns ; out[c,b,t] += sum_n ns * dec[c,n]
// Tiling: BM=64, BN=64, BK=16, 128 threads, per-thread 8x4.
#define BM 64
#define BN 64
#define BK 16
#define TM 8
#define TN 4

__global__ void __launch_bounds__(128, 1)
step_kernel(const float* __restrict__ W,
            const float* __restrict__ mask,
            const float* __restrict__ bias,
            const float* __restrict__ thr,
            const float* __restrict__ dec,
            float* __restrict__ out,
            int t) {
    __shared__ float As[BK][BM + 4];
    __shared__ float Bs[BK][BN + 4];

    const int n0 = blockIdx.x * BN;
    const int b0 = blockIdx.y * BM;
    const int tid = threadIdx.x;
    const int tx = tid & 15;   // n-direction (16)
    const int ty = tid >> 4;   // b-direction (8)
    const int lr = tid >> 1;        // 0..63 : tile row for loads
    const int lk = (tid & 1) << 3;  // 0 or 8 : k-offset for loads

    float acc[TM][TN];
#pragma unroll
    for (int i = 0; i < TM; i++)
#pragma unroll
        for (int j = 0; j < TN; j++) acc[i][j] = 0.0f;

    const float* Aptr = g_sprime + (size_t)(b0 + lr) * NN + lk;  // s'[b, k]
    const float* Bptr = W + (size_t)(n0 + lr) * NN + lk;         // W[n, k]

    for (int k0 = 0; k0 < NN; k0 += BK) {
        float4 a0 = *(const float4*)(Aptr + k0);
        float4 a1 = *(const float4*)(Aptr + k0 + 4);
        float4 w0 = *(const float4*)(Bptr + k0);
        float4 w1 = *(const float4*)(Bptr + k0 + 4);

        As[lk + 0][lr] = a0.x; As[lk + 1][lr] = a0.y;
        As[lk + 2][lr] = a0.z; As[lk + 3][lr] = a0.w;
        As[lk + 4][lr] = a1.x; As[lk + 5][lr] = a1.y;
        As[lk + 6][lr] = a1.z; As[lk + 7][lr] = a1.w;

        Bs[lk + 0][lr] = w0.x; Bs[lk + 1][lr] = w0.y;
        Bs[lk + 2][lr] = w0.z; Bs[lk + 3][lr] = w0.w;
        Bs[lk + 4][lr] = w1.x; Bs[lk + 5][lr] = w1.y;
        Bs[lk + 6][lr] = w1.z; Bs[lk + 7][lr] = w1.w;

        __syncthreads();

#pragma unroll
        for (int k = 0; k < BK; k++) {
            float av[TM], bv[TN];
            float4 xa = *(const float4*)&As[k][ty * TM];
            float4 xb = *(const float4*)&As[k][ty * TM + 4];
            av[0] = xa.x; av[1] = xa.y; av[2] = xa.z; av[3] = xa.w;
            av[4] = xb.x; av[5] = xb.y; av[6] = xb.z; av[7] = xb.w;
            float4 yb = *(const float4*)&Bs[k][tx * TN];
            bv[0] = yb.x; bv[1] = yb.y; bv[2] = yb.z; bv[3] = yb.w;
#pragma unroll
            for (int i = 0; i < TM; i++)
#pragma unroll
                for (int j = 0; j < TN; j++)
                    acc[i][j] = fmaf(av[i], bv[j], acc[i][j]);
        }
        __syncthreads();
    }

    // Epilogue: activation + state store + decoder partial sums
    float p0[TM], p1[TM];
#pragma unroll
    for (int i = 0; i < TM; i++) { p0[i] = 0.0f; p1[i] = 0.0f; }

#pragma unroll
    for (int j = 0; j < TN; j++) {
        int n = n0 + tx * TN + j;
        float mk = mask[n];
        float bi = bias[n];
        float th = thr[n];
        float d0 = dec[n];
        float d1 = dec[NN + n];
#pragma unroll
        for (int i = 0; i < TM; i++) {
            float z = SLOPE * (acc[i][j] - th);
            float sg = 1.0f / (1.0f + __expf(-z));
            float ns = mk * (bi + sg);
            acc[i][j] = ns;
            p0[i] = fmaf(ns, d0, p0[i]);
            p1[i] = fmaf(ns, d1, p1[i]);
        }
    }

    // Store new state (coalesced float4 per row)
#pragma unroll
    for (int i = 0; i < TM; i++) {
        float4 v = make_float4(acc[i][0], acc[i][1], acc[i][2], acc[i][3]);
        *(float4*)&g_state[(size_t)(b0 + ty * TM + i) * NN + n0 + tx * TN] = v;
    }

    // Reduce partial decoder sums across the 16 tx lanes (lane bits 0..3)
#pragma unroll
    for (int i = 0; i < TM; i++) {
#pragma unroll
        for (int off = 8; off >= 1; off >>= 1) {
            p0[i] += __shfl_xor_sync(0xffffffffu, p0[i], off);
            p1[i] += __shfl_xor_sync(0xffffffffu, p1[i], off);
        }
    }
    if (tx == 0) {
#pragma unroll
        for (int i = 0; i < TM; i++) {
            int b = b0 + ty * TM + i;
            atomicAdd(&out[b * TT + t], p0[i]);              // c = 0
            atomicAdd(&out[(BB + b) * TT + t], p1[i]);       // c = 1
        }
    }
}

// ---------------------------------------------------------------------------
extern "C" void kernel_launch(void* const* d_in, const int* in_sizes, int n_in,
                              void* d_out, int out_size) {
    const float* inputs = (const float*)d_in[0];  // [C,B,T]
    const float* state0 = (const float*)d_in[1];  // [B,N]
    const float* mask   = (const float*)d_in[2];  // [N]
    const float* enc    = (const float*)d_in[3];  // [C,N]
    const float* dec    = (const float*)d_in[4];  // [C,N]
    const float* W      = (const float*)d_in[5];  // [N,N]
    const float* bias   = (const float*)d_in[6];  // [N]
    const float* thr    = (const float*)d_in[7];  // [N]
    float* out = (float*)d_out;                   // [C,B,T] fp32

    zero_kernel<<<(CC * BB * TT + 255) / 256, 256>>>(out, CC * BB * TT);

    dim3 ggrid(NN / BN, BB / BM);  // (32, 4) = 128 blocks
    for (int t = 0; t < TT; t++) {
        prep_kernel<<<(BB * NN) / 256, 256>>>(state0, inputs, mask, enc, t);
        step_kernel<<<ggrid, 128>>>(W, mask, bias, thr, dec, out, t);
    }
}

// round 3
// speedup vs baseline: 1.0093x; 1.0093x over previous
#include <cuda_runtime.h>

// Problem constants (fixed by the dataset)
#define NN 2048   // reservoir size
#define BB 256    // batch
#define TT 256    // timesteps
#define CC 2      // channels
#define SLOPE 8.0f

// Scratch state buffers (allocation-free rule -> __device__ globals)
__device__ float g_state[BB * NN];   // state after each step
__device__ float g_sprime[BB * NN];  // s' = state + mask * ext

// ---------------------------------------------------------------------------
__global__ void zero_kernel(float* __restrict__ out, int n) {
    int i = blockIdx.x * blockDim.x + threadIdx.x;
    if (i < n) out[i] = 0.0f;
}

// ---------------------------------------------------------------------------
// s'[b,m] = s[b,m] + mask[m] * (x0[b]*enc[0,m] + x1[b]*enc[1,m])
__global__ void prep_kernel(const float* __restrict__ state0,
                            const float* __restrict__ inputs,
                            const float* __restrict__ mask,
                            const float* __restrict__ enc,
                            int t) {
    int i = blockIdx.x * blockDim.x + threadIdx.x;  // over B*N
    int b = i >> 11;        // / NN
    int m = i & (NN - 1);   // % NN
    const float* s = (t == 0) ? state0 : g_state;
    float x0 = inputs[b * TT + t];            // c=0 : (0*BB+b)*TT + t
    float x1 = inputs[(BB + b) * TT + t];     // c=1
    g_sprime[i] = s[i] + mask[m] * (x0 * enc[m] + x1 * enc[NN + m]);
}

// ---------------------------------------------------------------------------
// Fused step: pre = s' @ W^T ; ns = mask*(bias + sigmoid(SLOPE*(pre-thr)))
//             g_state = ns ; out[c,b,t] += sum_n ns * dec[c,n]
// Tiling: BM=64, BN=64, BK=16, 128 threads, per-thread 8x4.
#define BM 64
#define BN 64
#define BK 16
#define TM 8
#define TN 4

__global__ void __launch_bounds__(128, 1)
step_kernel(const float* __restrict__ W,
            const float* __restrict__ mask,
            const float* __restrict__ bias,
            const float* __restrict__ thr,
            const float* __restrict__ dec,
            float* __restrict__ out,
            int t) {
    __shared__ float As[BK][BM + 4];
    __shared__ float Bs[BK][BN + 4];

    const int n0 = blockIdx.x * BN;
    const int b0 = blockIdx.y * BM;
    const int tid = threadIdx.x;
    const int tx = tid & 15;   // n-direction (16)
    const int ty = tid >> 4;   // b-direction (8)
    const int lr = tid >> 1;        // 0..63 : tile row for loads
    const int lk = (tid & 1) << 3;  // 0 or 8 : k-offset for loads

    float acc[TM][TN];
#pragma unroll
    for (int i = 0; i < TM; i++)
#pragma unroll
        for (int j = 0; j < TN; j++) acc[i][j] = 0.0f;

    const float* Aptr = g_sprime + (size_t)(b0 + lr) * NN + lk;  // s'[b, k]
    const float* Bptr = W + (size_t)(n0 + lr) * NN + lk;         // W[n, k]

    for (int k0 = 0; k0 < NN; k0 += BK) {
        float4 a0 = *(const float4*)(Aptr + k0);
        float4 a1 = *(const float4*)(Aptr + k0 + 4);
        float4 w0 = *(const float4*)(Bptr + k0);
        float4 w1 = *(const float4*)(Bptr + k0 + 4);

        As[lk + 0][lr] = a0.x; As[lk + 1][lr] = a0.y;
        As[lk + 2][lr] = a0.z; As[lk + 3][lr] = a0.w;
        As[lk + 4][lr] = a1.x; As[lk + 5][lr] = a1.y;
        As[lk + 6][lr] = a1.z; As[lk + 7][lr] = a1.w;

        Bs[lk + 0][lr] = w0.x; Bs[lk + 1][lr] = w0.y;
        Bs[lk + 2][lr] = w0.z; Bs[lk + 3][lr] = w0.w;
        Bs[lk + 4][lr] = w1.x; Bs[lk + 5][lr] = w1.y;
        Bs[lk + 6][lr] = w1.z; Bs[lk + 7][lr] = w1.w;

        __syncthreads();

#pragma unroll
        for (int k = 0; k < BK; k++) {
            float av[TM], bv[TN];
            float4 xa = *(const float4*)&As[k][ty * TM];
            float4 xb = *(const float4*)&As[k][ty * TM + 4];
            av[0] = xa.x; av[1] = xa.y; av[2] = xa.z; av[3] = xa.w;
            av[4] = xb.x; av[5] = xb.y; av[6] = xb.z; av[7] = xb.w;
            float4 yb = *(const float4*)&Bs[k][tx * TN];
            bv[0] = yb.x; bv[1] = yb.y; bv[2] = yb.z; bv[3] = yb.w;
#pragma unroll
            for (int i = 0; i < TM; i++)
#pragma unroll
                for (int j = 0; j < TN; j++)
                    acc[i][j] = fmaf(av[i], bv[j], acc[i][j]);
        }
        __syncthreads();
    }

    // Epilogue: activation + state store + decoder partial sums
    float p0[TM], p1[TM];
#pragma unroll
    for (int i = 0; i < TM; i++) { p0[i] = 0.0f; p1[i] = 0.0f; }

#pragma unroll
    for (int j = 0; j < TN; j++) {
        int n = n0 + tx * TN + j;
        float mk = mask[n];
        float bi = bias[n];
        float th = thr[n];
        float d0 = dec[n];
        float d1 = dec[NN + n];
#pragma unroll
        for (int i = 0; i < TM; i++) {
            float z = SLOPE * (acc[i][j] - th);
            float sg = 1.0f / (1.0f + __expf(-z));
            float ns = mk * (bi + sg);
            acc[i][j] = ns;
            p0[i] = fmaf(ns, d0, p0[i]);
            p1[i] = fmaf(ns, d1, p1[i]);
        }
    }

    // Store new state (coalesced float4 per row)
#pragma unroll
    for (int i = 0; i < TM; i++) {
        float4 v = make_float4(acc[i][0], acc[i][1], acc[i][2], acc[i][3]);
        *(float4*)&g_state[(size_t)(b0 + ty * TM + i) * NN + n0 + tx * TN] = v;
    }

    // Reduce partial decoder sums across the 16 tx lanes (lane bits 0..3)
#pragma unroll
    for (int i = 0; i < TM; i++) {
#pragma unroll
        for (int off = 8; off >= 1; off >>= 1) {
            p0[i] += __shfl_xor_sync(0xffffffffu, p0[i], off);
            p1[i] += __shfl_xor_sync(0xffffffffu, p1[i], off);
        }
    }
    if (tx == 0) {
#pragma unroll
        for (int i = 0; i < TM; i++) {
            int b = b0 + ty * TM + i;
            atomicAdd(&out[b * TT + t], p0[i]);              // c = 0
            atomicAdd(&out[(BB + b) * TT + t], p1[i]);       // c = 1
        }
    }
}

// ---------------------------------------------------------------------------
extern "C" void kernel_launch(void* const* d_in, const int* in_sizes, int n_in,
                              void* d_out, int out_size) {
    const float* inputs = (const float*)d_in[0];  // [C,B,T]
    const float* state0 = (const float*)d_in[1];  // [B,N]
    const float* mask   = (const float*)d_in[2];  // [N]
    const float* enc    = (const float*)d_in[3];  // [C,N]
    const float* dec    = (const float*)d_in[4];  // [C,N]
    const float* W      = (const float*)d_in[5];  // [N,N]
    const float* bias   = (const float*)d_in[6];  // [N]
    const float* thr    = (const float*)d_in[7];  // [N]
    float* out = (float*)d_out;                   // [C,B,T] fp32

    zero_kernel<<<(CC * BB * TT + 255) / 256, 256>>>(out, CC * BB * TT);

    dim3 ggrid(NN / BN, BB / BM);  // (32, 4) = 128 blocks
    for (int t = 0; t < TT; t++) {
        prep_kernel<<<(BB * NN) / 256, 256>>>(state0, inputs, mask, enc, t);
        step_kernel<<<ggrid, 128>>>(W, mask, bias, thr, dec, out, t);
    }
}

// round 8
// speedup vs baseline: 3.2622x; 3.2321x over previous
#include <cuda_runtime.h>
#include <cuda_bf16.h>
#include <cstdint>

// Problem constants
#define NN 2048
#define BB 256
#define TT 256
#define CC 2
#define SLOPE 8.0f

// GEMM tiling: CTA 64x64, k-chunk 32, 128 threads (4 warps, 2x2)
#define BM 64
#define BN 64
#define BK 32
#define NIT (NN / BK)   // 64
#define THREADS 128

#define TILE_B (64 * 64)          // 4096 B per tile: 64 rows x 32 bf16 (64B/row)
#define STAGE_B (4 * TILE_B)      // Ah, Al, Bh, Bl = 16384 B
#define NSTAGE 3
#define SMEM_PAR 0                // 7 x 64 floats = 1792 B
#define SMEM_STAGE 2048
#define SMEM_TOTAL (SMEM_STAGE + NSTAGE * STAGE_B)  // 51200 B

// Scratch (allocation-free rule -> __device__ globals)
__device__ __align__(256) __nv_bfloat16 g_a_hi[BB * NN];
__device__ __align__(256) __nv_bfloat16 g_a_lo[BB * NN];
__device__ __align__(256) __nv_bfloat16 g_w_hi[NN * NN];
__device__ __align__(256) __nv_bfloat16 g_w_lo[NN * NN];

// ---------------------------------------------------------------------------
__device__ __forceinline__ uint32_t s2u(const void* p) {
    uint32_t a;
    asm("{ .reg .u64 t; cvta.to.shared.u64 t, %1; cvt.u32.u64 %0, t; }"
        : "=r"(a) : "l"(p));
    return a;
}

__device__ __forceinline__ void cp16(uint32_t dst, const void* src) {
    asm volatile("cp.async.cg.shared.global [%0], [%1], 16;\n"
                 :: "r"(dst), "l"(src));
}
#define CP_COMMIT() asm volatile("cp.async.commit_group;\n" ::: "memory")
#define CP_WAIT(n)  asm volatile("cp.async.wait_group %0;\n" :: "n"(n) : "memory")

__device__ __forceinline__ void ldsm4(uint32_t* r, uint32_t addr) {
    asm volatile("ldmatrix.sync.aligned.m8n8.x4.shared.b16 {%0,%1,%2,%3}, [%4];"
                 : "=r"(r[0]), "=r"(r[1]), "=r"(r[2]), "=r"(r[3]) : "r"(addr));
}

__device__ __forceinline__ void mma16816(float* c, const uint32_t* a,
                                         uint32_t b0, uint32_t b1) {
    asm volatile("mma.sync.aligned.m16n8k16.row.col.f32.bf16.bf16.f32 "
                 "{%0,%1,%2,%3}, {%4,%5,%6,%7}, {%8,%9}, {%0,%1,%2,%3};"
                 : "+f"(c[0]), "+f"(c[1]), "+f"(c[2]), "+f"(c[3])
                 : "r"(a[0]), "r"(a[1]), "r"(a[2]), "r"(a[3]),
                   "r"(b0), "r"(b1));
}

// ---------------------------------------------------------------------------
__global__ void zero_kernel(float* __restrict__ out, int n) {
    int i = blockIdx.x * blockDim.x + threadIdx.x;
    if (i < n) out[i] = 0.0f;
}

// W fp32 -> hi/lo bf16 (once per launch)
__global__ void wconv_kernel(const float* __restrict__ W) {
    int i = blockIdx.x * blockDim.x + threadIdx.x;
    if (i < NN * NN) {
        float w = W[i];
        __nv_bfloat16 h = __float2bfloat16_rn(w);
        g_w_hi[i] = h;
        g_w_lo[i] = __float2bfloat16_rn(w - __bfloat162float(h));
    }
}

// s'(0) = state0 + mask * ext(t=0), split hi/lo
__global__ void prep0_kernel(const float* __restrict__ state0,
                             const float* __restrict__ inputs,
                             const float* __restrict__ mask,
                             const float* __restrict__ enc) {
    int i = blockIdx.x * blockDim.x + threadIdx.x;
    int b = i >> 11;
    int n = i & (NN - 1);
    float x0 = inputs[b * TT];
    float x1 = inputs[(BB + b) * TT];
    float sp = state0[i] + mask[n] * (x0 * enc[n] + x1 * enc[NN + n]);
    __nv_bfloat16 h = __float2bfloat16_rn(sp);
    g_a_hi[i] = h;
    g_a_lo[i] = __float2bfloat16_rn(sp - __bfloat162float(h));
}

// ---------------------------------------------------------------------------
// Fused step kernel: pre = s'@W^T via 3x bf16 HMMA GEMM (hi*hi + hi*lo + lo*hi),
// sigmoid epilogue, decoder reduction into out, next-step s' hi/lo split.
__global__ void __launch_bounds__(THREADS, 1)
step_kernel(const float* __restrict__ inputs,
            const float* __restrict__ mask,
            const float* __restrict__ bias,
            const float* __restrict__ thr,
            const float* __restrict__ dec,
            const float* __restrict__ enc,
            float* __restrict__ out,
            int t) {
    extern __shared__ char smem[];
    const uint32_t sbase = s2u(smem);
    const int tid = threadIdx.x;
    const int wid = tid >> 5;
    const int lid = tid & 31;
    const int wm = wid >> 1;   // 0..1 : warp m index
    const int wn = wid & 1;    // 0..1 : warp n index
    const int n0 = blockIdx.x * BN;
    const int m0 = blockIdx.y * BM;

    // epilogue params into smem: [mask|bias|thr|dec0|dec1|enc0|enc1] x 64
    if (tid < 64) {
        float* pp = (float*)(smem + SMEM_PAR);
        int n = n0 + tid;
        pp[tid]       = mask[n];
        pp[64 + tid]  = bias[n];
        pp[128 + tid] = thr[n];
        pp[192 + tid] = dec[n];
        pp[256 + tid] = dec[NN + n];
        pp[320 + tid] = enc[n];
        pp[384 + tid] = enc[NN + n];
    }

    // Fill one pipeline stage with chunk c: Ah, Al (64 m-rows x 32 k) and
    // Bh, Bl (64 n-rows x 32 k). 16 KB = 1024 x cp16, 8 per thread.
    auto fill = [&](int c) {
        const uint32_t sb = sbase + SMEM_STAGE + (c % NSTAGE) * STAGE_B;
        const int k0 = c * BK;
#pragma unroll
        for (int j = 0; j < 8; j++) {
            int q = tid + j * THREADS;       // 0..1023
            int tile = q >> 8;               // 0:Ah 1:Al 2:Bh 3:Bl
            int w = q & 255;
            int row = w >> 2;
            int ch = w & 3;                  // 16B chunk within 64B row
            const __nv_bfloat16* src;
            if (tile == 0)      src = g_a_hi + (size_t)(m0 + row) * NN + k0 + ch * 8;
            else if (tile == 1) src = g_a_lo + (size_t)(m0 + row) * NN + k0 + ch * 8;
            else if (tile == 2) src = g_w_hi + (size_t)(n0 + row) * NN + k0 + ch * 8;
            else                src = g_w_lo + (size_t)(n0 + row) * NN + k0 + ch * 8;
            uint32_t dst = sb + tile * TILE_B + row * 64 +
                           ((ch ^ ((row >> 1) & 3)) << 4);  // conflict-free swizzle
            cp16(dst, src);
        }
        CP_COMMIT();
    };

    fill(0);
    fill(1);
    fill(2);

    float acc[2][4][4];  // [mi][n8 block q][4 accum regs]
#pragma unroll
    for (int i = 0; i < 2; i++)
#pragma unroll
        for (int q = 0; q < 4; q++)
#pragma unroll
            for (int r = 0; r < 4; r++) acc[i][q][r] = 0.0f;

    const int lrow8 = lid & 7;
    const int lgrp = lid >> 3;   // 0..3 : ldmatrix 8x8 sub-matrix index

#pragma unroll 1
    for (int c = 0; c < NIT; c++) {
        if (c < NIT - 2)       CP_WAIT(2);
        else if (c == NIT - 2) CP_WAIT(1);
        else                   CP_WAIT(0);
        __syncthreads();

        const uint32_t sb = sbase + SMEM_STAGE + (c % NSTAGE) * STAGE_B;

#pragma unroll
        for (int ks = 0; ks < 2; ks++) {   // two k16 steps per BK=32
            // A fragments: m16 x k16, x4 ldmatrix; (group&1) -> m8 half,
            // (group>>1) -> k8 half.
            uint32_t ah[2][4], al[2][4], bh[2][4], bl[2][4];
#pragma unroll
            for (int mi = 0; mi < 2; mi++) {
                int row = wm * 32 + mi * 16 + (lgrp & 1) * 8 + lrow8;
                int kch = ks * 2 + (lgrp >> 1);
                uint32_t off = row * 64 + ((kch ^ ((row >> 1) & 3)) << 4);
                ldsm4(ah[mi], sb + 0 * TILE_B + off);
                ldsm4(al[mi], sb + 1 * TILE_B + off);
            }
#pragma unroll
            for (int ni = 0; ni < 2; ni++) {
                int row = wn * 32 + ni * 16 + (lgrp & 1) * 8 + lrow8;
                int kch = ks * 2 + (lgrp >> 1);
                uint32_t off = row * 64 + ((kch ^ ((row >> 1) & 3)) << 4);
                ldsm4(bh[ni], sb + 2 * TILE_B + off);
                ldsm4(bl[ni], sb + 3 * TILE_B + off);
            }
#pragma unroll
            for (int mi = 0; mi < 2; mi++)
#pragma unroll
                for (int ni = 0; ni < 2; ni++)
#pragma unroll
                    for (int nh = 0; nh < 2; nh++) {
                        int q = ni * 2 + nh;
                        // B n8 frag for block nh: {r[nh] (k0-7), r[nh+2] (k8-15)}
                        mma16816(acc[mi][q], ah[mi], bh[ni][nh], bh[ni][nh + 2]);
                        mma16816(acc[mi][q], ah[mi], bl[ni][nh], bl[ni][nh + 2]);
                        mma16816(acc[mi][q], al[mi], bh[ni][nh], bh[ni][nh + 2]);
                    }
        }
        __syncthreads();
        if (c + NSTAGE < NIT) fill(c + NSTAGE);
    }

    // ---- Epilogue ----
    // acc[mi][q][r]: r0:(m=base+lid/4, n=nb), r1:(m,nb+1), r2:(m+8,nb), r3:(m+8,nb+1)
    // base = m0+wm*32+mi*16, nb = wn*32+q*8+2*(lid&3)
    const float* pp = (const float*)(smem + SMEM_PAR);
    const bool hasn = (t + 1 < TT);
#pragma unroll
    for (int mi = 0; mi < 2; mi++) {
#pragma unroll
        for (int h = 0; h < 2; h++) {
            int b = m0 + wm * 32 + mi * 16 + h * 8 + (lid >> 2);
            float x0 = 0.0f, x1 = 0.0f;
            if (hasn) {
                x0 = inputs[b * TT + t + 1];
                x1 = inputs[(BB + b) * TT + t + 1];
            }
            float p0 = 0.0f, p1 = 0.0f;
#pragma unroll
            for (int q = 0; q < 4; q++) {
                int nl = wn * 32 + q * 8 + ((lid & 3) << 1);
                float pre0 = acc[mi][q][h * 2 + 0];
                float pre1 = acc[mi][q][h * 2 + 1];
                float mk0 = pp[nl],     mk1 = pp[nl + 1];
                float z0 = SLOPE * (pre0 - pp[128 + nl]);
                float z1 = SLOPE * (pre1 - pp[128 + nl + 1]);
                float sg0 = 1.0f / (1.0f + __expf(-z0));
                float sg1 = 1.0f / (1.0f + __expf(-z1));
                float ns0 = mk0 * (pp[64 + nl] + sg0);
                float ns1 = mk1 * (pp[64 + nl + 1] + sg1);
                p0 = fmaf(ns0, pp[192 + nl], fmaf(ns1, pp[192 + nl + 1], p0));
                p1 = fmaf(ns0, pp[256 + nl], fmaf(ns1, pp[256 + nl + 1], p1));
                if (hasn) {
                    float sp0 = fmaf(mk0, fmaf(x0, pp[320 + nl], x1 * pp[384 + nl]), ns0);
                    float sp1 = fmaf(mk1, fmaf(x0, pp[320 + nl + 1], x1 * pp[384 + nl + 1]), ns1);
                    __nv_bfloat16 h0 = __float2bfloat16_rn(sp0);
                    __nv_bfloat16 h1 = __float2bfloat16_rn(sp1);
                    __nv_bfloat16 l0 = __float2bfloat16_rn(sp0 - __bfloat162float(h0));
                    __nv_bfloat16 l1 = __float2bfloat16_rn(sp1 - __bfloat162float(h1));
                    uint32_t hv = ((uint32_t)__bfloat16_as_ushort(h1) << 16) |
                                  (uint32_t)__bfloat16_as_ushort(h0);
                    uint32_t lv = ((uint32_t)__bfloat16_as_ushort(l1) << 16) |
                                  (uint32_t)__bfloat16_as_ushort(l0);
                    *(uint32_t*)(g_a_hi + (size_t)b * NN + n0 + nl) = hv;
                    *(uint32_t*)(g_a_lo + (size_t)b * NN + n0 + nl) = lv;
                }
            }
            // reduce decoder partials over the 4 lanes of the quad (n direction)
            p0 += __shfl_xor_sync(0xffffffffu, p0, 1);
            p0 += __shfl_xor_sync(0xffffffffu, p0, 2);
            p1 += __shfl_xor_sync(0xffffffffu, p1, 1);
            p1 += __shfl_xor_sync(0xffffffffu, p1, 2);
            if ((lid & 3) == 0) {
                atomicAdd(&out[b * TT + t], p0);               // c = 0
                atomicAdd(&out[(BB + b) * TT + t], p1);        // c = 1
            }
        }
    }
}

// ---------------------------------------------------------------------------
extern "C" void kernel_launch(void* const* d_in, const int* in_sizes, int n_in,
                              void* d_out, int out_size) {
    const float* inputs = (const float*)d_in[0];  // [C,B,T]
    const float* state0 = (const float*)d_in[1];  // [B,N]
    const float* mask   = (const float*)d_in[2];  // [N]
    const float* enc    = (const float*)d_in[3];  // [C,N]
    const float* dec    = (const float*)d_in[4];  // [C,N]
    const float* W      = (const float*)d_in[5];  // [N,N]
    const float* bias   = (const float*)d_in[6];  // [N]
    const float* thr    = (const float*)d_in[7];  // [N]
    float* out = (float*)d_out;                   // [C,B,T]

    cudaFuncSetAttribute(step_kernel,
                         cudaFuncAttributeMaxDynamicSharedMemorySize, SMEM_TOTAL);

    zero_kernel<<<(CC * BB * TT + 255) / 256, 256>>>(out, CC * BB * TT);
    wconv_kernel<<<(NN * NN + 255) / 256, 256>>>(W);
    prep0_kernel<<<(BB * NN + 255) / 256, 256>>>(state0, inputs, mask, enc);

    dim3 grid(NN / BN, BB / BM);  // (32, 4) = 128 CTAs
    for (int t = 0; t < TT; t++) {
        step_kernel<<<grid, THREADS, SMEM_TOTAL>>>(inputs, mask, bias, thr,
                                                   dec, enc, out, t);
    }
}

// round 9
// speedup vs baseline: 3.4251x; 1.0499x over previous
#include <cuda_runtime.h>
#include <cuda_bf16.h>
#include <cstdint>

// Problem constants
#define NN 2048
#define BB 256
#define TT 256
#define CC 2
#define SLOPE 8.0f

// GEMM tiling: CTA 64x64, k-chunk 32, 256 threads (8 warps, 2x4 warp grid)
#define BM 64
#define BN 64
#define BK 32
#define NIT (NN / BK)   // 64
#define THREADS 256

#define TILE_B (64 * 64)          // 4096 B per tile: 64 rows x 32 bf16 (64B/row)
#define STAGE_B (4 * TILE_B)      // Ah, Al, Bh, Bl = 16384 B
#define NSTAGE 3
#define SMEM_PAR 0                // 7 x 64 floats = 1792 B
#define SMEM_STAGE 2048
#define SMEM_TOTAL (SMEM_STAGE + NSTAGE * STAGE_B)  // 51200 B

// Scratch (allocation-free rule -> __device__ globals)
__device__ __align__(256) __nv_bfloat16 g_a_hi[BB * NN];
__device__ __align__(256) __nv_bfloat16 g_a_lo[BB * NN];
__device__ __align__(256) __nv_bfloat16 g_w_hi[NN * NN];
__device__ __align__(256) __nv_bfloat16 g_w_lo[NN * NN];

// ---------------------------------------------------------------------------
__device__ __forceinline__ uint32_t s2u(const void* p) {
    uint32_t a;
    asm("{ .reg .u64 t; cvta.to.shared.u64 t, %1; cvt.u32.u64 %0, t; }"
        : "=r"(a) : "l"(p));
    return a;
}

__device__ __forceinline__ void cp16(uint32_t dst, const void* src) {
    asm volatile("cp.async.cg.shared.global [%0], [%1], 16;\n"
                 :: "r"(dst), "l"(src));
}
#define CP_COMMIT() asm volatile("cp.async.commit_group;\n" ::: "memory")
#define CP_WAIT(n)  asm volatile("cp.async.wait_group %0;\n" :: "n"(n) : "memory")

__device__ __forceinline__ void ldsm4(uint32_t* r, uint32_t addr) {
    asm volatile("ldmatrix.sync.aligned.m8n8.x4.shared.b16 {%0,%1,%2,%3}, [%4];"
                 : "=r"(r[0]), "=r"(r[1]), "=r"(r[2]), "=r"(r[3]) : "r"(addr));
}

__device__ __forceinline__ void mma16816(float* c, const uint32_t* a,
                                         uint32_t b0, uint32_t b1) {
    asm volatile("mma.sync.aligned.m16n8k16.row.col.f32.bf16.bf16.f32 "
                 "{%0,%1,%2,%3}, {%4,%5,%6,%7}, {%8,%9}, {%0,%1,%2,%3};"
                 : "+f"(c[0]), "+f"(c[1]), "+f"(c[2]), "+f"(c[3])
                 : "r"(a[0]), "r"(a[1]), "r"(a[2]), "r"(a[3]),
                   "r"(b0), "r"(b1));
}

// ---------------------------------------------------------------------------
__global__ void zero_kernel(float* __restrict__ out, int n) {
    int i = blockIdx.x * blockDim.x + threadIdx.x;
    if (i < n) out[i] = 0.0f;
}

// W fp32 -> hi/lo bf16 (once per launch)
__global__ void wconv_kernel(const float* __restrict__ W) {
    int i = blockIdx.x * blockDim.x + threadIdx.x;
    if (i < NN * NN) {
        float w = W[i];
        __nv_bfloat16 h = __float2bfloat16_rn(w);
        g_w_hi[i] = h;
        g_w_lo[i] = __float2bfloat16_rn(w - __bfloat162float(h));
    }
}

// s'(0) = state0 + mask * ext(t=0), split hi/lo
__global__ void prep0_kernel(const float* __restrict__ state0,
                             const float* __restrict__ inputs,
                             const float* __restrict__ mask,
                             const float* __restrict__ enc) {
    int i = blockIdx.x * blockDim.x + threadIdx.x;
    int b = i >> 11;
    int n = i & (NN - 1);
    float x0 = inputs[b * TT];
    float x1 = inputs[(BB + b) * TT];
    float sp = state0[i] + mask[n] * (x0 * enc[n] + x1 * enc[NN + n]);
    __nv_bfloat16 h = __float2bfloat16_rn(sp);
    g_a_hi[i] = h;
    g_a_lo[i] = __float2bfloat16_rn(sp - __bfloat162float(h));
}

// ---------------------------------------------------------------------------
// Fused step kernel: pre = s'@W^T via 3x bf16 HMMA GEMM (hi*hi + hi*lo + lo*hi),
// sigmoid epilogue, decoder reduction into out, next-step s' hi/lo split.
// 8 warps: warp grid 2(m) x 4(n), warp tile 32x16.
__global__ void __launch_bounds__(THREADS, 1)
step_kernel(const float* __restrict__ inputs,
            const float* __restrict__ mask,
            const float* __restrict__ bias,
            const float* __restrict__ thr,
            const float* __restrict__ dec,
            const float* __restrict__ enc,
            float* __restrict__ out,
            int t) {
    extern __shared__ char smem[];
    const uint32_t sbase = s2u(smem);
    const int tid = threadIdx.x;
    const int wid = tid >> 5;
    const int lid = tid & 31;
    const int wm = wid >> 2;   // 0..1 : warp m index (32 rows each)
    const int wn = wid & 3;    // 0..3 : warp n index (16 cols each)
    const int n0 = blockIdx.x * BN;
    const int m0 = blockIdx.y * BM;

    // epilogue params into smem: [mask|bias|thr|dec0|dec1|enc0|enc1] x 64
    if (tid < 64) {
        float* pp = (float*)(smem + SMEM_PAR);
        int n = n0 + tid;
        pp[tid]       = mask[n];
        pp[64 + tid]  = bias[n];
        pp[128 + tid] = thr[n];
        pp[192 + tid] = dec[n];
        pp[256 + tid] = dec[NN + n];
        pp[320 + tid] = enc[n];
        pp[384 + tid] = enc[NN + n];
    }

    // Fill one pipeline stage with chunk c: Ah, Al (64 m-rows x 32 k) and
    // Bh, Bl (64 n-rows x 32 k). 16 KB = 1024 x cp16, 4 per thread.
    const int frow = tid >> 2;       // 0..63
    const int fch = tid & 3;         // 16B chunk within 64B row
    const uint32_t fdst = frow * 64 + ((fch ^ ((frow >> 1) & 3)) << 4);
    auto fill = [&](int c) {
        const uint32_t sb = sbase + SMEM_STAGE + (c % NSTAGE) * STAGE_B;
        const int k0 = c * BK;
        const size_t ko = (size_t)frow * NN + k0 + fch * 8;
        cp16(sb + 0 * TILE_B + fdst, g_a_hi + (size_t)m0 * NN + ko);
        cp16(sb + 1 * TILE_B + fdst, g_a_lo + (size_t)m0 * NN + ko);
        cp16(sb + 2 * TILE_B + fdst, g_w_hi + (size_t)n0 * NN + ko);
        cp16(sb + 3 * TILE_B + fdst, g_w_lo + (size_t)n0 * NN + ko);
        CP_COMMIT();
    };

    fill(0);
    fill(1);
    fill(2);

    float acc[2][2][4];  // [mi][nh][4 accum regs]
#pragma unroll
    for (int i = 0; i < 2; i++)
#pragma unroll
        for (int q = 0; q < 2; q++)
#pragma unroll
            for (int r = 0; r < 4; r++) acc[i][q][r] = 0.0f;

    const int lrow8 = lid & 7;
    const int lgrp = lid >> 3;   // 0..3 : ldmatrix 8x8 sub-matrix index

#pragma unroll 1
    for (int c = 0; c < NIT; c++) {
        if (c < NIT - 2)       CP_WAIT(2);
        else if (c == NIT - 2) CP_WAIT(1);
        else                   CP_WAIT(0);
        __syncthreads();

        const uint32_t sb = sbase + SMEM_STAGE + (c % NSTAGE) * STAGE_B;

        // Load ALL fragments for both k16 sub-steps (12 x ldmatrix.x4)
        uint32_t ah[2][2][4], al[2][2][4], bh[2][4], bl[2][4];  // [ks][mi]
#pragma unroll
        for (int ks = 0; ks < 2; ks++) {
            const int kch = ks * 2 + (lgrp >> 1);
#pragma unroll
            for (int mi = 0; mi < 2; mi++) {
                int row = wm * 32 + mi * 16 + (lgrp & 1) * 8 + lrow8;
                uint32_t off = row * 64 + ((kch ^ ((row >> 1) & 3)) << 4);
                ldsm4(ah[ks][mi], sb + 0 * TILE_B + off);
                ldsm4(al[ks][mi], sb + 1 * TILE_B + off);
            }
            {
                int row = wn * 16 + (lgrp & 1) * 8 + lrow8;
                uint32_t off = row * 64 + ((kch ^ ((row >> 1) & 3)) << 4);
                ldsm4(bh[ks], sb + 2 * TILE_B + off);
                ldsm4(bl[ks], sb + 3 * TILE_B + off);
            }
        }

        // 24 MMAs, product-pass-major: same accumulator revisited only every
        // 4 MMAs -> dependent HMMA chains are spread out.
#pragma unroll
        for (int ks = 0; ks < 2; ks++)
#pragma unroll
            for (int mi = 0; mi < 2; mi++)
#pragma unroll
                for (int nh = 0; nh < 2; nh++)
                    mma16816(acc[mi][nh], ah[ks][mi], bh[ks][nh], bh[ks][nh + 2]);
#pragma unroll
        for (int ks = 0; ks < 2; ks++)
#pragma unroll
            for (int mi = 0; mi < 2; mi++)
#pragma unroll
                for (int nh = 0; nh < 2; nh++)
                    mma16816(acc[mi][nh], ah[ks][mi], bl[ks][nh], bl[ks][nh + 2]);
#pragma unroll
        for (int ks = 0; ks < 2; ks++)
#pragma unroll
            for (int mi = 0; mi < 2; mi++)
#pragma unroll
                for (int nh = 0; nh < 2; nh++)
                    mma16816(acc[mi][nh], al[ks][mi], bh[ks][nh], bh[ks][nh + 2]);

        __syncthreads();
        if (c + NSTAGE < NIT) fill(c + NSTAGE);
    }

    // ---- Epilogue ----
    // acc[mi][nh][r]: r0:(m=base+lid/4, n=nb), r1:(m,nb+1), r2:(m+8,nb), r3:(m+8,nb+1)
    // base = m0+wm*32+mi*16, nb = wn*16+nh*8+2*(lid&3)
    const float* pp = (const float*)(smem + SMEM_PAR);
    const bool hasn = (t + 1 < TT);
#pragma unroll
    for (int mi = 0; mi < 2; mi++) {
#pragma unroll
        for (int h = 0; h < 2; h++) {
            int b = m0 + wm * 32 + mi * 16 + h * 8 + (lid >> 2);
            float x0 = 0.0f, x1 = 0.0f;
            if (hasn) {
                x0 = inputs[b * TT + t + 1];
                x1 = inputs[(BB + b) * TT + t + 1];
            }
            float p0 = 0.0f, p1 = 0.0f;
#pragma unroll
            for (int nh = 0; nh < 2; nh++) {
                int nl = wn * 16 + nh * 8 + ((lid & 3) << 1);
                float pre0 = acc[mi][nh][h * 2 + 0];
                float pre1 = acc[mi][nh][h * 2 + 1];
                float mk0 = pp[nl],     mk1 = pp[nl + 1];
                float z0 = SLOPE * (pre0 - pp[128 + nl]);
                float z1 = SLOPE * (pre1 - pp[128 + nl + 1]);
                float sg0 = 1.0f / (1.0f + __expf(-z0));
                float sg1 = 1.0f / (1.0f + __expf(-z1));
                float ns0 = mk0 * (pp[64 + nl] + sg0);
                float ns1 = mk1 * (pp[64 + nl + 1] + sg1);
                p0 = fmaf(ns0, pp[192 + nl], fmaf(ns1, pp[192 + nl + 1], p0));
                p1 = fmaf(ns0, pp[256 + nl], fmaf(ns1, pp[256 + nl + 1], p1));
                if (hasn) {
                    float sp0 = fmaf(mk0, fmaf(x0, pp[320 + nl], x1 * pp[384 + nl]), ns0);
                    float sp1 = fmaf(mk1, fmaf(x0, pp[320 + nl + 1], x1 * pp[384 + nl + 1]), ns1);
                    __nv_bfloat16 h0 = __float2bfloat16_rn(sp0);
                    __nv_bfloat16 h1 = __float2bfloat16_rn(sp1);
                    __nv_bfloat16 l0 = __float2bfloat16_rn(sp0 - __bfloat162float(h0));
                    __nv_bfloat16 l1 = __float2bfloat16_rn(sp1 - __bfloat162float(h1));
                    uint32_t hv = ((uint32_t)__bfloat16_as_ushort(h1) << 16) |
                                  (uint32_t)__bfloat16_as_ushort(h0);
                    uint32_t lv = ((uint32_t)__bfloat16_as_ushort(l1) << 16) |
                                  (uint32_t)__bfloat16_as_ushort(l0);
                    *(uint32_t*)(g_a_hi + (size_t)b * NN + n0 + nl) = hv;
                    *(uint32_t*)(g_a_lo + (size_t)b * NN + n0 + nl) = lv;
                }
            }
            // reduce decoder partials over the 4 lanes of the quad (n direction)
            p0 += __shfl_xor_sync(0xffffffffu, p0, 1);
            p0 += __shfl_xor_sync(0xffffffffu, p0, 2);
            p1 += __shfl_xor_sync(0xffffffffu, p1, 1);
            p1 += __shfl_xor_sync(0xffffffffu, p1, 2);
            if ((lid & 3) == 0) {
                atomicAdd(&out[b * TT + t], p0);               // c = 0
                atomicAdd(&out[(BB + b) * TT + t], p1);        // c = 1
            }
        }
    }
}

// ---------------------------------------------------------------------------
extern "C" void kernel_launch(void* const* d_in, const int* in_sizes, int n_in,
                              void* d_out, int out_size) {
    const float* inputs = (const float*)d_in[0];  // [C,B,T]
    const float* state0 = (const float*)d_in[1];  // [B,N]
    const float* mask   = (const float*)d_in[2];  // [N]
    const float* enc    = (const float*)d_in[3];  // [C,N]
    const float* dec    = (const float*)d_in[4];  // [C,N]
    const float* W      = (const float*)d_in[5];  // [N,N]
    const float* bias   = (const float*)d_in[6];  // [N]
    const float* thr    = (const float*)d_in[7];  // [N]
    float* out = (float*)d_out;                   // [C,B,T]

    cudaFuncSetAttribute(step_kernel,
                         cudaFuncAttributeMaxDynamicSharedMemorySize, SMEM_TOTAL);

    zero_kernel<<<(CC * BB * TT + 255) / 256, 256>>>(out, CC * BB * TT);
    wconv_kernel<<<(NN * NN + 255) / 256, 256>>>(W);
    prep0_kernel<<<(BB * NN + 255) / 256, 256>>>(state0, inputs, mask, enc);

    dim3 grid(NN / BN, BB / BM);  // (32, 4) = 128 CTAs
    for (int t = 0; t < TT; t++) {
        step_kernel<<<grid, THREADS, SMEM_TOTAL>>>(inputs, mask, bias, thr,
                                                   dec, enc, out, t);
    }
}

// round 10
// speedup vs baseline: 4.2204x; 1.2322x over previous
#include <cuda_runtime.h>
#include <cuda_bf16.h>
#include <cstdint>

// Problem constants
#define NN 2048
#define BB 256
#define TT 256
#define CC 2
#define SLOPE 8.0f

// GEMM tiling: CTA 64x64, k-chunk 64, 256 threads (8 warps = 2 wg x (2x2))
#define BM 64
#define BN 64
#define BK 64
#define NIT (NN / BK)   // 32
#define THREADS 256

#define TILE_B (64 * 128)         // 8192 B: 64 rows x 64 bf16 (128B/row)
#define STAGE_B (4 * TILE_B)      // Ah, Al, Bh, Bl = 32768 B
#define NSTAGE 4
#define SMEM_PAR 0                // 7 x 64 floats = 1792 B
#define SMEM_STAGE 2048
#define SMEM_TOTAL (SMEM_STAGE + NSTAGE * STAGE_B)  // 133120 B

// Scratch, double-buffered in t-parity (allocation-free rule)
__device__ __align__(256) __nv_bfloat16 g_a_hi[2 * BB * NN];
__device__ __align__(256) __nv_bfloat16 g_a_lo[2 * BB * NN];
__device__ __align__(256) __nv_bfloat16 g_w_hi[NN * NN];
__device__ __align__(256) __nv_bfloat16 g_w_lo[NN * NN];

// ---------------------------------------------------------------------------
__device__ __forceinline__ uint32_t s2u(const void* p) {
    uint32_t a;
    asm("{ .reg .u64 t; cvta.to.shared.u64 t, %1; cvt.u32.u64 %0, t; }"
        : "=r"(a) : "l"(p));
    return a;
}

__device__ __forceinline__ void cp16(uint32_t dst, const void* src) {
    asm volatile("cp.async.cg.shared.global [%0], [%1], 16;\n"
                 :: "r"(dst), "l"(src));
}
#define CP_COMMIT() asm volatile("cp.async.commit_group;\n" ::: "memory")
#define CP_WAIT(n)  asm volatile("cp.async.wait_group %0;\n" :: "n"(n) : "memory")

__device__ __forceinline__ void ldsm4(uint32_t* r, uint32_t addr) {
    asm volatile("ldmatrix.sync.aligned.m8n8.x4.shared.b16 {%0,%1,%2,%3}, [%4];"
                 : "=r"(r[0]), "=r"(r[1]), "=r"(r[2]), "=r"(r[3]) : "r"(addr));
}

__device__ __forceinline__ void mma16816(float* c, const uint32_t* a,
                                         uint32_t b0, uint32_t b1) {
    asm volatile("mma.sync.aligned.m16n8k16.row.col.f32.bf16.bf16.f32 "
                 "{%0,%1,%2,%3}, {%4,%5,%6,%7}, {%8,%9}, {%0,%1,%2,%3};"
                 : "+f"(c[0]), "+f"(c[1]), "+f"(c[2]), "+f"(c[3])
                 : "r"(a[0]), "r"(a[1]), "r"(a[2]), "r"(a[3]),
                   "r"(b0), "r"(b1));
}

// ---------------------------------------------------------------------------
__global__ void zero_kernel(float* __restrict__ out, int n) {
    int i = blockIdx.x * blockDim.x + threadIdx.x;
    if (i < n) out[i] = 0.0f;
}

// W fp32 -> hi/lo bf16 (once per launch)
__global__ void wconv_kernel(const float* __restrict__ W) {
    int i = blockIdx.x * blockDim.x + threadIdx.x;
    if (i < NN * NN) {
        float w = W[i];
        __nv_bfloat16 h = __float2bfloat16_rn(w);
        g_w_hi[i] = h;
        g_w_lo[i] = __float2bfloat16_rn(w - __bfloat162float(h));
    }
}

// s'(0) = state0 + mask * ext(t=0), split hi/lo, into parity-0 buffer
__global__ void prep0_kernel(const float* __restrict__ state0,
                             const float* __restrict__ inputs,
                             const float* __restrict__ mask,
                             const float* __restrict__ enc) {
    int i = blockIdx.x * blockDim.x + threadIdx.x;
    int b = i >> 11;
    int n = i & (NN - 1);
    float x0 = inputs[b * TT];
    float x1 = inputs[(BB + b) * TT];
    float sp = state0[i] + mask[n] * (x0 * enc[n] + x1 * enc[NN + n]);
    __nv_bfloat16 h = __float2bfloat16_rn(sp);
    g_a_hi[i] = h;
    g_a_lo[i] = __float2bfloat16_rn(sp - __bfloat162float(h));
}

// ---------------------------------------------------------------------------
// Fused step kernel: pre = s'@W^T via 3x bf16 HMMA (hi*hi + hi*lo + lo*hi),
// warp-level k-split (wg0: k[0:32), wg1: k[32:64) of each BK=64 chunk),
// smem reduction, sigmoid epilogue, decoder atomics, next-state hi/lo split.
__global__ void __launch_bounds__(THREADS, 1)
step_kernel(const float* __restrict__ inputs,
            const float* __restrict__ mask,
            const float* __restrict__ bias,
            const float* __restrict__ thr,
            const float* __restrict__ dec,
            const float* __restrict__ enc,
            float* __restrict__ out,
            int t) {
    extern __shared__ char smem[];
    const uint32_t sbase = s2u(smem);
    const int tid = threadIdx.x;
    const int wid = tid >> 5;
    const int lid = tid & 31;
    const int wg = wid >> 2;    // 0..1 : k-split group
    const int wq = wid & 3;     // position within group
    const int wm = wq >> 1;     // 0..1 : 32-row m tile
    const int wn = wq & 1;      // 0..1 : 32-col n tile
    const int n0 = blockIdx.x * BN;
    const int m0 = blockIdx.y * BM;

    const __nv_bfloat16* a_hi_r = g_a_hi + (size_t)(t & 1) * (BB * NN);
    const __nv_bfloat16* a_lo_r = g_a_lo + (size_t)(t & 1) * (BB * NN);
    __nv_bfloat16* a_hi_w = g_a_hi + (size_t)((t + 1) & 1) * (BB * NN);
    __nv_bfloat16* a_lo_w = g_a_lo + (size_t)((t + 1) & 1) * (BB * NN);

    // epilogue params into smem: [mask|bias|thr|dec0|dec1|enc0|enc1] x 64
    if (tid < 64) {
        float* pp = (float*)(smem + SMEM_PAR);
        int n = n0 + tid;
        pp[tid]       = mask[n];
        pp[64 + tid]  = bias[n];
        pp[128 + tid] = thr[n];
        pp[192 + tid] = dec[n];
        pp[256 + tid] = dec[NN + n];
        pp[320 + tid] = enc[n];
        pp[384 + tid] = enc[NN + n];
    }

    // Fill stage (c % 4) with chunk c: Ah, Al, Bh, Bl; 64 rows x 128B each.
    // 2048 x cp16 total, 8 per thread. Swizzle: chunk ^ (row & 7).
    auto fill = [&](int c) {
        const uint32_t sb = sbase + SMEM_STAGE + (c & (NSTAGE - 1)) * STAGE_B;
        const int k0 = c * BK;
#pragma unroll
        for (int j = 0; j < 8; j++) {
            int q = tid + j * THREADS;       // 0..2047
            int tile = q >> 9;               // 0:Ah 1:Al 2:Bh 3:Bl
            int w = q & 511;
            int row = w >> 3;
            int ch = w & 7;                  // 16B chunk within 128B row
            const __nv_bfloat16* src;
            size_t ko = (size_t)row * NN + k0 + ch * 8;
            if (tile == 0)      src = a_hi_r + (size_t)m0 * NN + ko;
            else if (tile == 1) src = a_lo_r + (size_t)m0 * NN + ko;
            else if (tile == 2) src = g_w_hi + (size_t)n0 * NN + ko;
            else                src = g_w_lo + (size_t)n0 * NN + ko;
            uint32_t dst = sb + tile * TILE_B + row * 128 +
                           ((ch ^ (row & 7)) << 4);
            cp16(dst, src);
        }
        CP_COMMIT();
    };

    fill(0);
    fill(1);
    fill(2);

    float acc[2][4][4];  // [mi][q = ni*2+nh][4 accum regs]
#pragma unroll
    for (int i = 0; i < 2; i++)
#pragma unroll
        for (int q = 0; q < 4; q++)
#pragma unroll
            for (int r = 0; r < 4; r++) acc[i][q][r] = 0.0f;

    const int lrow8 = lid & 7;
    const int lgrp = lid >> 3;   // ldmatrix 8x8 sub-matrix index

#pragma unroll 1
    for (int c = 0; c < NIT; c++) {
        if (c < NIT - 2)       CP_WAIT(2);
        else if (c == NIT - 2) CP_WAIT(1);
        else                   CP_WAIT(0);
        __syncthreads();

        if (c + 3 < NIT) fill(c + 3);   // targets stage consumed last iter

        const uint32_t sb = sbase + SMEM_STAGE + (c & (NSTAGE - 1)) * STAGE_B;

#pragma unroll
        for (int ks = 0; ks < 2; ks++) {  // two k16 steps in this wg's k32
            const int kch = wg * 4 + ks * 2 + (lgrp >> 1);
            uint32_t ah[2][4], al[2][4], bh[2][4], bl[2][4];
#pragma unroll
            for (int mi = 0; mi < 2; mi++) {
                int row = wm * 32 + mi * 16 + (lgrp & 1) * 8 + lrow8;
                uint32_t off = row * 128 + ((kch ^ (row & 7)) << 4);
                ldsm4(ah[mi], sb + 0 * TILE_B + off);
                ldsm4(al[mi], sb + 1 * TILE_B + off);
            }
#pragma unroll
            for (int ni = 0; ni < 2; ni++) {
                int row = wn * 32 + ni * 16 + (lgrp & 1) * 8 + lrow8;
                uint32_t off = row * 128 + ((kch ^ (row & 7)) << 4);
                ldsm4(bh[ni], sb + 2 * TILE_B + off);
                ldsm4(bl[ni], sb + 3 * TILE_B + off);
            }
            // 24 MMAs, product-pass-major: accumulators revisited every 8
#pragma unroll
            for (int mi = 0; mi < 2; mi++)
#pragma unroll
                for (int q = 0; q < 4; q++)
                    mma16816(acc[mi][q], ah[mi], bh[q >> 1][q & 1],
                             bh[q >> 1][(q & 1) + 2]);
#pragma unroll
            for (int mi = 0; mi < 2; mi++)
#pragma unroll
                for (int q = 0; q < 4; q++)
                    mma16816(acc[mi][q], ah[mi], bl[q >> 1][q & 1],
                             bl[q >> 1][(q & 1) + 2]);
#pragma unroll
            for (int mi = 0; mi < 2; mi++)
#pragma unroll
                for (int q = 0; q < 4; q++)
                    mma16816(acc[mi][q], al[mi], bh[q >> 1][q & 1],
                             bh[q >> 1][(q & 1) + 2]);
        }
    }

    // ---- Cross-warpgroup reduction: wg1 accs -> wg0 via smem ----
    __syncthreads();
    float* red = (float*)(smem + SMEM_STAGE);   // 16KB, reuses stage area
    if (wg == 1) {
        const float* af = &acc[0][0][0];
        int base = wq * 32 + lid;               // 0..127
#pragma unroll
        for (int r = 0; r < 32; r++) red[r * 128 + base] = af[r];
    }
    __syncthreads();
    if (wg == 1) return;  // wg1 done

    {
        float* af = &acc[0][0][0];
        int base = wq * 32 + lid;
#pragma unroll
        for (int r = 0; r < 32; r++) af[r] += red[r * 128 + base];
    }

    // ---- Epilogue (wg0 only: 4 warps, each 32x32 tile) ----
    // acc[mi][q][r]: r0:(m, nb), r1:(m, nb+1), r2:(m+8, nb), r3:(m+8, nb+1)
    // m = m0+wm*32+mi*16+(lid>>2), nb = wn*32+q*8+2*(lid&3)
    const float* pp = (const float*)(smem + SMEM_PAR);
    const bool hasn = (t + 1 < TT);
#pragma unroll
    for (int mi = 0; mi < 2; mi++) {
#pragma unroll
        for (int h = 0; h < 2; h++) {
            int b = m0 + wm * 32 + mi * 16 + h * 8 + (lid >> 2);
            float x0 = 0.0f, x1 = 0.0f;
            if (hasn) {
                x0 = inputs[b * TT + t + 1];
                x1 = inputs[(BB + b) * TT + t + 1];
            }
            float p0 = 0.0f, p1 = 0.0f;
#pragma unroll
            for (int q = 0; q < 4; q++) {
                int nl = wn * 32 + q * 8 + ((lid & 3) << 1);
                float pre0 = acc[mi][q][h * 2 + 0];
                float pre1 = acc[mi][q][h * 2 + 1];
                float mk0 = pp[nl],     mk1 = pp[nl + 1];
                float z0 = SLOPE * (pre0 - pp[128 + nl]);
                float z1 = SLOPE * (pre1 - pp[128 + nl + 1]);
                float sg0 = 1.0f / (1.0f + __expf(-z0));
                float sg1 = 1.0f / (1.0f + __expf(-z1));
                float ns0 = mk0 * (pp[64 + nl] + sg0);
                float ns1 = mk1 * (pp[64 + nl + 1] + sg1);
                p0 = fmaf(ns0, pp[192 + nl], fmaf(ns1, pp[192 + nl + 1], p0));
                p1 = fmaf(ns0, pp[256 + nl], fmaf(ns1, pp[256 + nl + 1], p1));
                if (hasn) {
                    float sp0 = fmaf(mk0, fmaf(x0, pp[320 + nl], x1 * pp[384 + nl]), ns0);
                    float sp1 = fmaf(mk1, fmaf(x0, pp[320 + nl + 1], x1 * pp[384 + nl + 1]), ns1);
                    __nv_bfloat16 h0 = __float2bfloat16_rn(sp0);
                    __nv_bfloat16 h1 = __float2bfloat16_rn(sp1);
                    __nv_bfloat16 l0 = __float2bfloat16_rn(sp0 - __bfloat162float(h0));
                    __nv_bfloat16 l1 = __float2bfloat16_rn(sp1 - __bfloat162float(h1));
                    uint32_t hv = ((uint32_t)__bfloat16_as_ushort(h1) << 16) |
                                  (uint32_t)__bfloat16_as_ushort(h0);
                    uint32_t lv = ((uint32_t)__bfloat16_as_ushort(l1) << 16) |
                                  (uint32_t)__bfloat16_as_ushort(l0);
                    *(uint32_t*)(a_hi_w + (size_t)b * NN + n0 + nl) = hv;
                    *(uint32_t*)(a_lo_w + (size_t)b * NN + n0 + nl) = lv;
                }
            }
            // reduce decoder partials over the quad (n direction)
            p0 += __shfl_xor_sync(0xffffffffu, p0, 1);
            p0 += __shfl_xor_sync(0xffffffffu, p0, 2);
            p1 += __shfl_xor_sync(0xffffffffu, p1, 1);
            p1 += __shfl_xor_sync(0xffffffffu, p1, 2);
            if ((lid & 3) == 0) {
                atomicAdd(&out[b * TT + t], p0);               // c = 0
                atomicAdd(&out[(BB + b) * TT + t], p1);        // c = 1
            }
        }
    }
}

// ---------------------------------------------------------------------------
extern "C" void kernel_launch(void* const* d_in, const int* in_sizes, int n_in,
                              void* d_out, int out_size) {
    const float* inputs = (const float*)d_in[0];  // [C,B,T]
    const float* state0 = (const float*)d_in[1];  // [B,N]
    const float* mask   = (const float*)d_in[2];  // [N]
    const float* enc    = (const float*)d_in[3];  // [C,N]
    const float* dec    = (const float*)d_in[4];  // [C,N]
    const float* W      = (const float*)d_in[5];  // [N,N]
    const float* bias   = (const float*)d_in[6];  // [N]
    const float* thr    = (const float*)d_in[7];  // [N]
    float* out = (float*)d_out;                   // [C,B,T]

    cudaFuncSetAttribute(step_kernel,
                         cudaFuncAttributeMaxDynamicSharedMemorySize, SMEM_TOTAL);

    zero_kernel<<<(CC * BB * TT + 255) / 256, 256>>>(out, CC * BB * TT);
    wconv_kernel<<<(NN * NN + 255) / 256, 256>>>(W);
    prep0_kernel<<<(BB * NN + 255) / 256, 256>>>(state0, inputs, mask, enc);

    dim3 grid(NN / BN, BB / BM);  // (32, 4) = 128 CTAs
    for (int t = 0; t < TT; t++) {
        step_kernel<<<grid, THREADS, SMEM_TOTAL>>>(inputs, mask, bias, thr,
                                                   dec, enc, out, t);
    }
}

// round 11
// speedup vs baseline: 4.3009x; 1.0191x over previous
#include <cuda_runtime.h>
#include <cuda_bf16.h>
#include <cstdint>

// Problem constants
#define NN 2048
#define BB 256
#define TT 256
#define CC 2
#define SLOPE 8.0f

// GEMM tiling: CTA 64x64, k-chunk 64, 512 threads (16 warps = 4 wg x (2x2))
#define BM 64
#define BN 64
#define BK 64
#define NIT (NN / BK)   // 32
#define THREADS 512

#define TILE_B (64 * 128)         // 8192 B: 64 rows x 64 bf16 (128B/row)
#define STAGE_B (4 * TILE_B)      // Ah, Al, Bh, Bl = 32768 B
#define NSTAGE 4
#define SMEM_PAR 0                // 7 x 64 floats = 1792 B
#define SMEM_STAGE 2048
#define SMEM_TOTAL (SMEM_STAGE + NSTAGE * STAGE_B)  // 133120 B

// Scratch, double-buffered in t-parity (allocation-free rule)
__device__ __align__(256) __nv_bfloat16 g_a_hi[2 * BB * NN];
__device__ __align__(256) __nv_bfloat16 g_a_lo[2 * BB * NN];
__device__ __align__(256) __nv_bfloat16 g_w_hi[NN * NN];
__device__ __align__(256) __nv_bfloat16 g_w_lo[NN * NN];

// ---------------------------------------------------------------------------
__device__ __forceinline__ uint32_t s2u(const void* p) {
    uint32_t a;
    asm("{ .reg .u64 t; cvta.to.shared.u64 t, %1; cvt.u32.u64 %0, t; }"
        : "=r"(a) : "l"(p));
    return a;
}

__device__ __forceinline__ void cp16(uint32_t dst, const void* src) {
    asm volatile("cp.async.cg.shared.global [%0], [%1], 16;\n"
                 :: "r"(dst), "l"(src));
}
#define CP_COMMIT() asm volatile("cp.async.commit_group;\n" ::: "memory")
#define CP_WAIT(n)  asm volatile("cp.async.wait_group %0;\n" :: "n"(n) : "memory")

__device__ __forceinline__ void ldsm4(uint32_t* r, uint32_t addr) {
    asm volatile("ldmatrix.sync.aligned.m8n8.x4.shared.b16 {%0,%1,%2,%3}, [%4];"
                 : "=r"(r[0]), "=r"(r[1]), "=r"(r[2]), "=r"(r[3]) : "r"(addr));
}

__device__ __forceinline__ void mma16816(float* c, const uint32_t* a,
                                         uint32_t b0, uint32_t b1) {
    asm volatile("mma.sync.aligned.m16n8k16.row.col.f32.bf16.bf16.f32 "
                 "{%0,%1,%2,%3}, {%4,%5,%6,%7}, {%8,%9}, {%0,%1,%2,%3};"
                 : "+f"(c[0]), "+f"(c[1]), "+f"(c[2]), "+f"(c[3])
                 : "r"(a[0]), "r"(a[1]), "r"(a[2]), "r"(a[3]),
                   "r"(b0), "r"(b1));
}

// ---------------------------------------------------------------------------
__global__ void zero_kernel(float* __restrict__ out, int n) {
    int i = blockIdx.x * blockDim.x + threadIdx.x;
    if (i < n) out[i] = 0.0f;
}

// W fp32 -> hi/lo bf16 (once per launch)
__global__ void wconv_kernel(const float* __restrict__ W) {
    int i = blockIdx.x * blockDim.x + threadIdx.x;
    if (i < NN * NN) {
        float w = W[i];
        __nv_bfloat16 h = __float2bfloat16_rn(w);
        g_w_hi[i] = h;
        g_w_lo[i] = __float2bfloat16_rn(w - __bfloat162float(h));
    }
}

// s'(0) = state0 + mask * ext(t=0), split hi/lo, into parity-0 buffer
__global__ void prep0_kernel(const float* __restrict__ state0,
                             const float* __restrict__ inputs,
                             const float* __restrict__ mask,
                             const float* __restrict__ enc) {
    int i = blockIdx.x * blockDim.x + threadIdx.x;
    int b = i >> 11;
    int n = i & (NN - 1);
    float x0 = inputs[b * TT];
    float x1 = inputs[(BB + b) * TT];
    float sp = state0[i] + mask[n] * (x0 * enc[n] + x1 * enc[NN + n]);
    __nv_bfloat16 h = __float2bfloat16_rn(sp);
    g_a_hi[i] = h;
    g_a_lo[i] = __float2bfloat16_rn(sp - __bfloat162float(h));
}

// ---------------------------------------------------------------------------
// Fused step kernel: pre = s'@W^T via 3x bf16 HMMA (hi*hi + hi*lo + lo*hi).
// 16 warps = 4 k-split warpgroups x (2x2) 32x32 warp tiles; 4-way smem
// reduction; distributed sigmoid/decoder/state epilogue across all threads.
__global__ void __launch_bounds__(THREADS, 1)
step_kernel(const float* __restrict__ inputs,
            const float* __restrict__ mask,
            const float* __restrict__ bias,
            const float* __restrict__ thr,
            const float* __restrict__ dec,
            const float* __restrict__ enc,
            float* __restrict__ out,
            int t) {
    extern __shared__ char smem[];
    const uint32_t sbase = s2u(smem);
    const int tid = threadIdx.x;
    const int wid = tid >> 5;
    const int lid = tid & 31;
    const int wg = wid >> 2;    // 0..3 : k16 slice within BK=64 chunk
    const int wq = wid & 3;
    const int wm = wq >> 1;     // 0..1 : 32-row m tile
    const int wn = wq & 1;      // 0..1 : 32-col n tile
    const int n0 = blockIdx.x * BN;
    const int m0 = blockIdx.y * BM;

    const __nv_bfloat16* a_hi_r = g_a_hi + (size_t)(t & 1) * (BB * NN);
    const __nv_bfloat16* a_lo_r = g_a_lo + (size_t)(t & 1) * (BB * NN);
    __nv_bfloat16* a_hi_w = g_a_hi + (size_t)((t + 1) & 1) * (BB * NN);
    __nv_bfloat16* a_lo_w = g_a_lo + (size_t)((t + 1) & 1) * (BB * NN);

    // epilogue params into smem: [mask|bias|thr|dec0|dec1|enc0|enc1] x 64
    if (tid < 64) {
        float* pp = (float*)(smem + SMEM_PAR);
        int n = n0 + tid;
        pp[tid]       = mask[n];
        pp[64 + tid]  = bias[n];
        pp[128 + tid] = thr[n];
        pp[192 + tid] = dec[n];
        pp[256 + tid] = dec[NN + n];
        pp[320 + tid] = enc[n];
        pp[384 + tid] = enc[NN + n];
    }

    // Fill stage (c % 4) with chunk c: Ah, Al, Bh, Bl; 64 rows x 128B each.
    // 2048 x cp16 total, 4 per thread. Swizzle: chunk ^ (row & 7).
    auto fill = [&](int c) {
        const uint32_t sb = sbase + SMEM_STAGE + (c & (NSTAGE - 1)) * STAGE_B;
        const int k0 = c * BK;
#pragma unroll
        for (int j = 0; j < 4; j++) {
            int q = tid + j * THREADS;       // 0..2047
            int tile = q >> 9;               // 0:Ah 1:Al 2:Bh 3:Bl
            int w = q & 511;
            int row = w >> 3;
            int ch = w & 7;                  // 16B chunk within 128B row
            const __nv_bfloat16* src;
            size_t ko = (size_t)row * NN + k0 + ch * 8;
            if (tile == 0)      src = a_hi_r + (size_t)m0 * NN + ko;
            else if (tile == 1) src = a_lo_r + (size_t)m0 * NN + ko;
            else if (tile == 2) src = g_w_hi + (size_t)n0 * NN + ko;
            else                src = g_w_lo + (size_t)n0 * NN + ko;
            uint32_t dst = sb + tile * TILE_B + row * 128 +
                           ((ch ^ (row & 7)) << 4);
            cp16(dst, src);
        }
        CP_COMMIT();
    };

    fill(0);
    fill(1);
    fill(2);

    float acc[2][4][4];  // [mi][q = ni*2+nh][4 accum regs]
#pragma unroll
    for (int i = 0; i < 2; i++)
#pragma unroll
        for (int q = 0; q < 4; q++)
#pragma unroll
            for (int r = 0; r < 4; r++) acc[i][q][r] = 0.0f;

    const int lrow8 = lid & 7;
    const int lgrp = lid >> 3;   // ldmatrix 8x8 sub-matrix index
    const int kch = (wg << 1) | (lgrp >> 1);  // this wg's k16 slice chunks

#pragma unroll 1
    for (int c = 0; c < NIT; c++) {
        if (c < NIT - 2)       CP_WAIT(2);
        else if (c == NIT - 2) CP_WAIT(1);
        else                   CP_WAIT(0);
        __syncthreads();

        if (c + 3 < NIT) fill(c + 3);   // targets stage consumed last iter

        const uint32_t sb = sbase + SMEM_STAGE + (c & (NSTAGE - 1)) * STAGE_B;

        uint32_t ah[2][4], al[2][4], bh[2][4], bl[2][4];
#pragma unroll
        for (int mi = 0; mi < 2; mi++) {
            int row = wm * 32 + mi * 16 + (lgrp & 1) * 8 + lrow8;
            uint32_t off = row * 128 + ((kch ^ (row & 7)) << 4);
            ldsm4(ah[mi], sb + 0 * TILE_B + off);
            ldsm4(al[mi], sb + 1 * TILE_B + off);
        }
#pragma unroll
        for (int ni = 0; ni < 2; ni++) {
            int row = wn * 32 + ni * 16 + (lgrp & 1) * 8 + lrow8;
            uint32_t off = row * 128 + ((kch ^ (row & 7)) << 4);
            ldsm4(bh[ni], sb + 2 * TILE_B + off);
            ldsm4(bl[ni], sb + 3 * TILE_B + off);
        }
        // 24 MMAs, product-pass-major: accumulators revisited every 8
#pragma unroll
        for (int mi = 0; mi < 2; mi++)
#pragma unroll
            for (int q = 0; q < 4; q++)
                mma16816(acc[mi][q], ah[mi], bh[q >> 1][q & 1],
                         bh[q >> 1][(q & 1) + 2]);
#pragma unroll
        for (int mi = 0; mi < 2; mi++)
#pragma unroll
            for (int q = 0; q < 4; q++)
                mma16816(acc[mi][q], ah[mi], bl[q >> 1][q & 1],
                         bl[q >> 1][(q & 1) + 2]);
#pragma unroll
        for (int mi = 0; mi < 2; mi++)
#pragma unroll
            for (int q = 0; q < 4; q++)
                mma16816(acc[mi][q], al[mi], bh[q >> 1][q & 1],
                         bh[q >> 1][(q & 1) + 2]);
    }

    // ---- Dump all accumulators to smem in (wg, m, n) layout ----
    __syncthreads();
    float* red = (float*)(smem + SMEM_STAGE);   // 4 x 16KB, reuses stage area
    {
        const int mb = wm * 32 + (lid >> 2);
        const int nb = wn * 32 + ((lid & 3) << 1);
        float* rg = red + (wg << 12);           // wg * 4096
#pragma unroll
        for (int mi = 0; mi < 2; mi++)
#pragma unroll
            for (int q = 0; q < 4; q++)
#pragma unroll
                for (int rr = 0; rr < 4; rr++) {
                    int m = mb + mi * 16 + ((rr >> 1) << 3);
                    int n = nb + q * 8 + (rr & 1);
                    rg[m * 64 + n] = acc[mi][q][rr];
                }
    }
    __syncthreads();

    // ---- Distributed epilogue: thread -> (row em, 8 cols at en) ----
    const float* pp = (const float*)(smem + SMEM_PAR);
    const bool hasn = (t + 1 < TT);
    const int em = tid >> 3;          // 0..63
    const int en = (tid & 7) << 3;    // 0,8,...,56
    const int b = m0 + em;

    float pre[8];
    {
        const float* r0 = red + em * 64 + en;
        float4 u0 = *(const float4*)(r0);
        float4 u1 = *(const float4*)(r0 + 4);
#pragma unroll
        for (int g = 1; g < 4; g++) {
            const float* rg = r0 + (g << 12);
            float4 v0 = *(const float4*)(rg);
            float4 v1 = *(const float4*)(rg + 4);
            u0.x += v0.x; u0.y += v0.y; u0.z += v0.z; u0.w += v0.w;
            u1.x += v1.x; u1.y += v1.y; u1.z += v1.z; u1.w += v1.w;
        }
        pre[0] = u0.x; pre[1] = u0.y; pre[2] = u0.z; pre[3] = u0.w;
        pre[4] = u1.x; pre[5] = u1.y; pre[6] = u1.z; pre[7] = u1.w;
    }

    float x0 = 0.0f, x1 = 0.0f;
    if (hasn) {
        x0 = inputs[b * TT + t + 1];
        x1 = inputs[(BB + b) * TT + t + 1];
    }
    float p0 = 0.0f, p1 = 0.0f;
    __nv_bfloat16 hb[8], lb[8];
#pragma unroll
    for (int j = 0; j < 8; j++) {
        int nl = en + j;
        float mk = pp[nl];
        float z = SLOPE * (pre[j] - pp[128 + nl]);
        float sg = 1.0f / (1.0f + __expf(-z));
        float ns = mk * (pp[64 + nl] + sg);
        p0 = fmaf(ns, pp[192 + nl], p0);
        p1 = fmaf(ns, pp[256 + nl], p1);
        float sp = fmaf(mk, fmaf(x0, pp[320 + nl], x1 * pp[384 + nl]), ns);
        __nv_bfloat16 h = __float2bfloat16_rn(sp);
        hb[j] = h;
        lb[j] = __float2bfloat16_rn(sp - __bfloat162float(h));
    }
    if (hasn) {
        *(uint4*)(a_hi_w + (size_t)b * NN + n0 + en) = *(uint4*)hb;
        *(uint4*)(a_lo_w + (size_t)b * NN + n0 + en) = *(uint4*)lb;
    }

    // reduce decoder partials over the 8 lanes covering this row
    p0 += __shfl_xor_sync(0xffffffffu, p0, 1);
    p0 += __shfl_xor_sync(0xffffffffu, p0, 2);
    p0 += __shfl_xor_sync(0xffffffffu, p0, 4);
    p1 += __shfl_xor_sync(0xffffffffu, p1, 1);
    p1 += __shfl_xor_sync(0xffffffffu, p1, 2);
    p1 += __shfl_xor_sync(0xffffffffu, p1, 4);
    if ((lid & 7) == 0) {
        atomicAdd(&out[b * TT + t], p0);               // c = 0
        atomicAdd(&out[(BB + b) * TT + t], p1);        // c = 1
    }
}

// ---------------------------------------------------------------------------
extern "C" void kernel_launch(void* const* d_in, const int* in_sizes, int n_in,
                              void* d_out, int out_size) {
    const float* inputs = (const float*)d_in[0];  // [C,B,T]
    const float* state0 = (const float*)d_in[1];  // [B,N]
    const float* mask   = (const float*)d_in[2];  // [N]
    const float* enc    = (const float*)d_in[3];  // [C,N]
    const float* dec    = (const float*)d_in[4];  // [C,N]
    const float* W      = (const float*)d_in[5];  // [N,N]
    const float* bias   = (const float*)d_in[6];  // [N]
    const float* thr    = (const float*)d_in[7];  // [N]
    float* out = (float*)d_out;                   // [C,B,T]

    cudaFuncSetAttribute(step_kernel,
                         cudaFuncAttributeMaxDynamicSharedMemorySize, SMEM_TOTAL);

    zero_kernel<<<(CC * BB * TT + 255) / 256, 256>>>(out, CC * BB * TT);
    wconv_kernel<<<(NN * NN + 255) / 256, 256>>>(W);
    prep0_kernel<<<(BB * NN + 255) / 256, 256>>>(state0, inputs, mask, enc);

    dim3 grid(NN / BN, BB / BM);  // (32, 4) = 128 CTAs
    for (int t = 0; t < TT; t++) {
        step_kernel<<<grid, THREADS, SMEM_TOTAL>>>(inputs, mask, bias, thr,
                                                   dec, enc, out, t);
    }
}

// round 12
// speedup vs baseline: 4.7724x; 1.1096x over previous
#include <cuda_runtime.h>
#include <cuda_bf16.h>
#include <cstdint>

// Problem constants
#define NN 2048
#define BB 256
#define TT 256
#define CC 2
#define SLOPE 8.0f

// GEMM tiling: CTA 64x64, k-chunk 64, 512 threads (16 warps = 4 wg x (2x2))
#define BM 64
#define BN 64
#define BK 64
#define NIT (NN / BK)   // 32
#define THREADS 512

#define TILE_B (64 * 128)         // 8192 B: 64 rows x 64 bf16 (128B/row)
#define STAGE_B (4 * TILE_B)      // Ah, Al, Bh, Bl = 32768 B
#define NSTAGE 4
#define SMEM_PAR 0                // 7 x 64 floats = 1792 B
#define SMEM_STAGE 2048
#define SMEM_TOTAL (SMEM_STAGE + NSTAGE * STAGE_B)  // 133120 B

// Scratch, double-buffered in t-parity (allocation-free rule)
__device__ __align__(256) __nv_bfloat16 g_a_hi[2 * BB * NN];
__device__ __align__(256) __nv_bfloat16 g_a_lo[2 * BB * NN];
__device__ __align__(256) __nv_bfloat16 g_w_hi[NN * NN];
__device__ __align__(256) __nv_bfloat16 g_w_lo[NN * NN];

// ---------------------------------------------------------------------------
__device__ __forceinline__ uint32_t s2u(const void* p) {
    uint32_t a;
    asm("{ .reg .u64 t; cvta.to.shared.u64 t, %1; cvt.u32.u64 %0, t; }"
        : "=r"(a) : "l"(p));
    return a;
}

__device__ __forceinline__ void cp16(uint32_t dst, const void* src) {
    asm volatile("cp.async.cg.shared.global [%0], [%1], 16;\n"
                 :: "r"(dst), "l"(src));
}
#define CP_COMMIT() asm volatile("cp.async.commit_group;\n" ::: "memory")
#define CP_WAIT(n)  asm volatile("cp.async.wait_group %0;\n" :: "n"(n) : "memory")

__device__ __forceinline__ void ldsm4(uint32_t* r, uint32_t addr) {
    asm volatile("ldmatrix.sync.aligned.m8n8.x4.shared.b16 {%0,%1,%2,%3}, [%4];"
                 : "=r"(r[0]), "=r"(r[1]), "=r"(r[2]), "=r"(r[3]) : "r"(addr));
}

__device__ __forceinline__ void mma16816(float* c, const uint32_t* a,
                                         uint32_t b0, uint32_t b1) {
    asm volatile("mma.sync.aligned.m16n8k16.row.col.f32.bf16.bf16.f32 "
                 "{%0,%1,%2,%3}, {%4,%5,%6,%7}, {%8,%9}, {%0,%1,%2,%3};"
                 : "+f"(c[0]), "+f"(c[1]), "+f"(c[2]), "+f"(c[3])
                 : "r"(a[0]), "r"(a[1]), "r"(a[2]), "r"(a[3]),
                   "r"(b0), "r"(b1));
}

// ---------------------------------------------------------------------------
__global__ void zero_kernel(float* __restrict__ out, int n) {
    int i = blockIdx.x * blockDim.x + threadIdx.x;
    if (i < n) out[i] = 0.0f;
}

// W fp32 -> hi/lo bf16 (once per launch)
__global__ void wconv_kernel(const float* __restrict__ W) {
    int i = blockIdx.x * blockDim.x + threadIdx.x;
    if (i < NN * NN) {
        float w = W[i];
        __nv_bfloat16 h = __float2bfloat16_rn(w);
        g_w_hi[i] = h;
        g_w_lo[i] = __float2bfloat16_rn(w - __bfloat162float(h));
    }
}

// s'(0) = state0 + mask * ext(t=0), split hi/lo, into parity-0 buffer
__global__ void prep0_kernel(const float* __restrict__ state0,
                             const float* __restrict__ inputs,
                             const float* __restrict__ mask,
                             const float* __restrict__ enc) {
    int i = blockIdx.x * blockDim.x + threadIdx.x;
    int b = i >> 11;
    int n = i & (NN - 1);
    float x0 = inputs[b * TT];
    float x1 = inputs[(BB + b) * TT];
    float sp = state0[i] + mask[n] * (x0 * enc[n] + x1 * enc[NN + n]);
    __nv_bfloat16 h = __float2bfloat16_rn(sp);
    g_a_hi[i] = h;
    g_a_lo[i] = __float2bfloat16_rn(sp - __bfloat162float(h));
}

// ---------------------------------------------------------------------------
// Fused step kernel: pre = s'@W^T via 3x bf16 HMMA (hi*hi + hi*lo + lo*hi).
// 16 warps = 4 k-split warpgroups x (2x2) 32x32 warp tiles.
// Register-pipelined fragments: hh-pass MMAs fire right after the barrier
// using fragments prefetched last iteration; al/bl and next ah/bh load behind.
__global__ void __launch_bounds__(THREADS, 1)
step_kernel(const float* __restrict__ inputs,
            const float* __restrict__ mask,
            const float* __restrict__ bias,
            const float* __restrict__ thr,
            const float* __restrict__ dec,
            const float* __restrict__ enc,
            float* __restrict__ out,
            int t) {
    extern __shared__ char smem[];
    const uint32_t sbase = s2u(smem);
    const int tid = threadIdx.x;
    const int wid = tid >> 5;
    const int lid = tid & 31;
    const int wg = wid >> 2;    // 0..3 : k16 slice within BK=64 chunk
    const int wq = wid & 3;
    const int wm = wq >> 1;     // 0..1 : 32-row m tile
    const int wn = wq & 1;      // 0..1 : 32-col n tile
    const int n0 = blockIdx.x * BN;
    const int m0 = blockIdx.y * BM;

    const __nv_bfloat16* a_hi_r = g_a_hi + (size_t)(t & 1) * (BB * NN);
    const __nv_bfloat16* a_lo_r = g_a_lo + (size_t)(t & 1) * (BB * NN);
    __nv_bfloat16* a_hi_w = g_a_hi + (size_t)((t + 1) & 1) * (BB * NN);
    __nv_bfloat16* a_lo_w = g_a_lo + (size_t)((t + 1) & 1) * (BB * NN);

    // epilogue params into smem: [mask|bias|thr|dec0|dec1|enc0|enc1] x 64
    if (tid < 64) {
        float* pp = (float*)(smem + SMEM_PAR);
        int n = n0 + tid;
        pp[tid]       = mask[n];
        pp[64 + tid]  = bias[n];
        pp[128 + tid] = thr[n];
        pp[192 + tid] = dec[n];
        pp[256 + tid] = dec[NN + n];
        pp[320 + tid] = enc[n];
        pp[384 + tid] = enc[NN + n];
    }

    // ---- Hoisted fill addressing (THREADS==512 -> tile j, row=tid>>3, ch=tid&7)
    const int frow = tid >> 3;
    const int fch = tid & 7;
    const uint32_t fdst = frow * 128 + ((fch ^ (frow & 7)) << 4);
    const __nv_bfloat16* pAh = a_hi_r + (size_t)(m0 + frow) * NN + fch * 8;
    const __nv_bfloat16* pAl = a_lo_r + (size_t)(m0 + frow) * NN + fch * 8;
    const __nv_bfloat16* pWh = g_w_hi + (size_t)(n0 + frow) * NN + fch * 8;
    const __nv_bfloat16* pWl = g_w_lo + (size_t)(n0 + frow) * NN + fch * 8;
    uint32_t fstage = 0;  // rotating stage for fills (chunks issued in order)

    auto fill = [&]() {
        const uint32_t sb = sbase + SMEM_STAGE + fstage * STAGE_B;
        cp16(sb + 0 * TILE_B + fdst, pAh);
        cp16(sb + 1 * TILE_B + fdst, pAl);
        cp16(sb + 2 * TILE_B + fdst, pWh);
        cp16(sb + 3 * TILE_B + fdst, pWl);
        CP_COMMIT();
        pAh += BK; pAl += BK; pWh += BK; pWl += BK;
        fstage = (fstage + 1) & (NSTAGE - 1);
    };

    fill();
    fill();
    fill();

    // ---- Hoisted ldsm offsets (constants: kch, rows fixed per thread) ----
    const int lrow8 = lid & 7;
    const int lgrp = lid >> 3;
    const int kch = (wg << 1) | (lgrp >> 1);
    uint32_t aoff[2], boff[2];
#pragma unroll
    for (int mi = 0; mi < 2; mi++) {
        int row = wm * 32 + mi * 16 + (lgrp & 1) * 8 + lrow8;
        aoff[mi] = row * 128 + ((kch ^ (row & 7)) << 4);
    }
#pragma unroll
    for (int ni = 0; ni < 2; ni++) {
        int row = wn * 32 + ni * 16 + (lgrp & 1) * 8 + lrow8;
        boff[ni] = row * 128 + ((kch ^ (row & 7)) << 4);
    }

    float acc[2][4][4];
#pragma unroll
    for (int i = 0; i < 2; i++)
#pragma unroll
        for (int q = 0; q < 4; q++)
#pragma unroll
            for (int r = 0; r < 4; r++) acc[i][q][r] = 0.0f;

    // Preload ah/bh fragments for chunk 0
    uint32_t ahb[2][2][4], bhb[2][2][4];   // double-buffered [c&1]
    CP_WAIT(2);
    __syncthreads();
    {
        const uint32_t sb = sbase + SMEM_STAGE;  // stage 0
#pragma unroll
        for (int mi = 0; mi < 2; mi++) ldsm4(ahb[0][mi], sb + 0 * TILE_B + aoff[mi]);
#pragma unroll
        for (int ni = 0; ni < 2; ni++) ldsm4(bhb[0][ni], sb + 2 * TILE_B + boff[ni]);
    }

#pragma unroll 2
    for (int c = 0; c < NIT; c++) {
        const int cur = c & 1;
        const int nxt = cur ^ 1;
        const uint32_t sb = sbase + SMEM_STAGE + (c & (NSTAGE - 1)) * STAGE_B;
        const uint32_t sbn = sbase + SMEM_STAGE + ((c + 1) & (NSTAGE - 1)) * STAGE_B;

        CP_WAIT(1);          // stage c and c+1 complete (own groups)
        __syncthreads();     // publish fills; protect stage (c-1)&3 reuse

        // lo fragments of chunk c (latency hidden behind hh pass)
        uint32_t al[2][4], bl[2][4];
#pragma unroll
        for (int mi = 0; mi < 2; mi++) ldsm4(al[mi], sb + 1 * TILE_B + aoff[mi]);
#pragma unroll
        for (int ni = 0; ni < 2; ni++) ldsm4(bl[ni], sb + 3 * TILE_B + boff[ni]);

        // pass 1: hh (fragments already in registers)
#pragma unroll
        for (int mi = 0; mi < 2; mi++)
#pragma unroll
            for (int q = 0; q < 4; q++)
                mma16816(acc[mi][q], ahb[cur][mi], bhb[cur][q >> 1][q & 1],
                         bhb[cur][q >> 1][(q & 1) + 2]);

        if (c + 3 < NIT) fill();

        // prefetch hh fragments of chunk c+1 (hidden behind passes 2/3)
        if (c + 1 < NIT) {
#pragma unroll
            for (int mi = 0; mi < 2; mi++)
                ldsm4(ahb[nxt][mi], sbn + 0 * TILE_B + aoff[mi]);
#pragma unroll
            for (int ni = 0; ni < 2; ni++)
                ldsm4(bhb[nxt][ni], sbn + 2 * TILE_B + boff[ni]);
        }

        // pass 2: hi * lo
#pragma unroll
        for (int mi = 0; mi < 2; mi++)
#pragma unroll
            for (int q = 0; q < 4; q++)
                mma16816(acc[mi][q], ahb[cur][mi], bl[q >> 1][q & 1],
                         bl[q >> 1][(q & 1) + 2]);
        // pass 3: lo * hi
#pragma unroll
        for (int mi = 0; mi < 2; mi++)
#pragma unroll
            for (int q = 0; q < 4; q++)
                mma16816(acc[mi][q], al[mi], bhb[cur][q >> 1][q & 1],
                         bhb[cur][q >> 1][(q & 1) + 2]);
    }

    // ---- Dump all accumulators to smem in (wg, m, n) layout ----
    __syncthreads();
    float* red = (float*)(smem + SMEM_STAGE);   // 4 x 16KB, reuses stage area
    {
        const int mb = wm * 32 + (lid >> 2);
        const int nb = wn * 32 + ((lid & 3) << 1);
        float* rg = red + (wg << 12);           // wg * 4096
#pragma unroll
        for (int mi = 0; mi < 2; mi++)
#pragma unroll
            for (int q = 0; q < 4; q++)
#pragma unroll
                for (int rr = 0; rr < 4; rr++) {
                    int m = mb + mi * 16 + ((rr >> 1) << 3);
                    int n = nb + q * 8 + (rr & 1);
                    rg[m * 64 + n] = acc[mi][q][rr];
                }
    }
    __syncthreads();

    // ---- Distributed epilogue: thread -> (row em, 8 cols at en) ----
    const float* pp = (const float*)(smem + SMEM_PAR);
    const bool hasn = (t + 1 < TT);
    const int em = tid >> 3;          // 0..63
    const int en = (tid & 7) << 3;    // 0,8,...,56
    const int b = m0 + em;

    float pre[8];
    {
        const float* r0 = red + em * 64 + en;
        float4 u0 = *(const float4*)(r0);
        float4 u1 = *(const float4*)(r0 + 4);
#pragma unroll
        for (int g = 1; g < 4; g++) {
            const float* rg = r0 + (g << 12);
            float4 v0 = *(const float4*)(rg);
            float4 v1 = *(const float4*)(rg + 4);
            u0.x += v0.x; u0.y += v0.y; u0.z += v0.z; u0.w += v0.w;
            u1.x += v1.x; u1.y += v1.y; u1.z += v1.z; u1.w += v1.w;
        }
        pre[0] = u0.x; pre[1] = u0.y; pre[2] = u0.z; pre[3] = u0.w;
        pre[4] = u1.x; pre[5] = u1.y; pre[6] = u1.z; pre[7] = u1.w;
    }

    float x0 = 0.0f, x1 = 0.0f;
    if (hasn) {
        x0 = inputs[b * TT + t + 1];
        x1 = inputs[(BB + b) * TT + t + 1];
    }
    float p0 = 0.0f, p1 = 0.0f;
    __nv_bfloat16 hb[8], lb[8];
#pragma unroll
    for (int j = 0; j < 8; j++) {
        int nl = en + j;
        float mk = pp[nl];
        float z = SLOPE * (pre[j] - pp[128 + nl]);
        float sg = 1.0f / (1.0f + __expf(-z));
        float ns = mk * (pp[64 + nl] + sg);
        p0 = fmaf(ns, pp[192 + nl], p0);
        p1 = fmaf(ns, pp[256 + nl], p1);
        float sp = fmaf(mk, fmaf(x0, pp[320 + nl], x1 * pp[384 + nl]), ns);
        __nv_bfloat16 h = __float2bfloat16_rn(sp);
        hb[j] = h;
        lb[j] = __float2bfloat16_rn(sp - __bfloat162float(h));
    }
    if (hasn) {
        *(uint4*)(a_hi_w + (size_t)b * NN + n0 + en) = *(uint4*)hb;
        *(uint4*)(a_lo_w + (size_t)b * NN + n0 + en) = *(uint4*)lb;
    }

    // reduce decoder partials over the 8 lanes covering this row
    p0 += __shfl_xor_sync(0xffffffffu, p0, 1);
    p0 += __shfl_xor_sync(0xffffffffu, p0, 2);
    p0 += __shfl_xor_sync(0xffffffffu, p0, 4);
    p1 += __shfl_xor_sync(0xffffffffu, p1, 1);
    p1 += __shfl_xor_sync(0xffffffffu, p1, 2);
    p1 += __shfl_xor_sync(0xffffffffu, p1, 4);
    if ((lid & 7) == 0) {
        atomicAdd(&out[b * TT + t], p0);               // c = 0
        atomicAdd(&out[(BB + b) * TT + t], p1);        // c = 1
    }
}

// ---------------------------------------------------------------------------
extern "C" void kernel_launch(void* const* d_in, const int* in_sizes, int n_in,
                              void* d_out, int out_size) {
    const float* inputs = (const float*)d_in[0];  // [C,B,T]
    const float* state0 = (const float*)d_in[1];  // [B,N]
    const float* mask   = (const float*)d_in[2];  // [N]
    const float* enc    = (const float*)d_in[3];  // [C,N]
    const float* dec    = (const float*)d_in[4];  // [C,N]
    const float* W      = (const float*)d_in[5];  // [N,N]
    const float* bias   = (const float*)d_in[6];  // [N]
    const float* thr    = (const float*)d_in[7];  // [N]
    float* out = (float*)d_out;                   // [C,B,T]

    cudaFuncSetAttribute(step_kernel,
                         cudaFuncAttributeMaxDynamicSharedMemorySize, SMEM_TOTAL);

    zero_kernel<<<(CC * BB * TT + 255) / 256, 256>>>(out, CC * BB * TT);
    wconv_kernel<<<(NN * NN + 255) / 256, 256>>>(W);
    prep0_kernel<<<(BB * NN + 255) / 256, 256>>>(state0, inputs, mask, enc);

    dim3 grid(NN / BN, BB / BM);  // (32, 4) = 128 CTAs
    for (int t = 0; t < TT; t++) {
        step_kernel<<<grid, THREADS, SMEM_TOTAL>>>(inputs, mask, bias, thr,
                                                   dec, enc, out, t);
    }
}